// round 1
// baseline (speedup 1.0000x reference)
#include <cuda_runtime.h>

#define T_TOK 4096
#define D_DIM 1024
#define H_DIM 2048
#define E_EXP 8
#define K_TOP 2
#define RMAX (T_TOK * K_TOP)   // 8192 routed rows total

// ---------------- scratch (device globals: no allocation allowed) ----------------
__device__ int   g_counts[E_EXP];
__device__ int   g_offsets[E_EXP + 1];
__device__ int   g_cursor[E_EXP];
__device__ int   g_is64;
__device__ int   g_tok[RMAX];
__device__ float g_gw[RMAX];
__device__ float g_act[(size_t)RMAX * H_DIM];   // 64 MB fc1 activations (compact rows)

// ---------------- small kernels ----------------
__global__ void zero_y_kernel(float4* y4, int n4) {
    int i = blockIdx.x * blockDim.x + threadIdx.x;
    if (i < n4) y4[i] = make_float4(0.f, 0.f, 0.f, 0.f);
}

__global__ void route_reset_kernel() {
    int t = threadIdx.x;
    if (t < E_EXP) { g_counts[t] = 0; g_cursor[t] = 0; }
    if (t == 0) g_is64 = 1;
}

// Detect int64 vs int32 indices: for int64 data (values 0..7), every odd 32-bit
// word is 0. For int32 data, odd words are random indices (some nonzero).
__global__ void detect_idx_kernel(const int* __restrict__ idx32) {
    int i = blockIdx.x * 256 + threadIdx.x;
    if (i < RMAX && (i & 1) && idx32[i] != 0) g_is64 = 0;
}

__device__ __forceinline__ int load_expert(const void* idxp, int i) {
    if (g_is64) return (int)((const long long*)idxp)[i];
    return ((const int*)idxp)[i];
}

__global__ void route_count_kernel(const void* __restrict__ idxp) {
    int i = blockIdx.x * 256 + threadIdx.x;
    if (i < RMAX) {
        int e = load_expert(idxp, i);
        atomicAdd(&g_counts[e], 1);
    }
}

__global__ void route_scan_kernel() {
    int s = 0;
    for (int e = 0; e < E_EXP; e++) { g_offsets[e] = s; s += g_counts[e]; }
    g_offsets[E_EXP] = s;
}

__global__ void route_place_kernel(const void* __restrict__ idxp,
                                   const float* __restrict__ w) {
    int i = blockIdx.x * 256 + threadIdx.x;
    if (i < RMAX) {
        int e = load_expert(idxp, i);
        int p = atomicAdd(&g_cursor[e], 1);
        int slot = g_offsets[e] + p;
        g_tok[slot] = i / K_TOP;
        g_gw[slot]  = w[i];
    }
}

// ---------------- fc1 + fused SwiGLU ----------------
// C tile: 128 gathered rows x 64 act cols. B tile packs 64 u-rows (n = j0+s)
// and 64 gate-rows (n = H + j0 + s) so SwiGLU fuses in the epilogue.
__global__ __launch_bounds__(256) void fc1_glu_kernel(const float* __restrict__ x,
                                                      const float* __restrict__ W1) {
    int e  = blockIdx.z;
    int Me = g_counts[e];
    int m0 = blockIdx.x * 128;
    if (m0 >= Me) return;
    int base = g_offsets[e];
    int j0   = blockIdx.y * 64;
    const float* W1e = W1 + (size_t)e * (2 * H_DIM) * D_DIM;

    __shared__ float As[16][132];
    __shared__ float Bs[16][132];

    int tid = threadIdx.x;
    int tm = tid >> 4;          // 0..15 -> 8 m-rows each
    int tn = tid & 15;          // 0..15 -> 4 act cols each

    int lr = tid >> 2;          // 0..63 loader row
    int lc = (tid & 3) * 4;     // k offset within 16

    int rA0 = lr, rA1 = lr + 64;
    const float* xA0 = (m0 + rA0 < Me) ? x + (size_t)g_tok[base + m0 + rA0] * D_DIM + lc : nullptr;
    const float* xA1 = (m0 + rA1 < Me) ? x + (size_t)g_tok[base + m0 + rA1] * D_DIM + lc : nullptr;
    const float* bp0 = W1e + (size_t)(j0 + lr) * D_DIM + lc;           // u row
    const float* bp1 = W1e + (size_t)(H_DIM + j0 + lr) * D_DIM + lc;   // gate row

    float acc_u[8][4], acc_g[8][4];
    #pragma unroll
    for (int i = 0; i < 8; i++)
        #pragma unroll
        for (int j = 0; j < 4; j++) { acc_u[i][j] = 0.f; acc_g[i][j] = 0.f; }

    for (int k0 = 0; k0 < D_DIM; k0 += 16) {
        float4 a0 = xA0 ? *(const float4*)(xA0 + k0) : make_float4(0,0,0,0);
        float4 a1 = xA1 ? *(const float4*)(xA1 + k0) : make_float4(0,0,0,0);
        float4 b0 = *(const float4*)(bp0 + k0);
        float4 b1 = *(const float4*)(bp1 + k0);
        __syncthreads();
        As[lc+0][rA0] = a0.x; As[lc+1][rA0] = a0.y; As[lc+2][rA0] = a0.z; As[lc+3][rA0] = a0.w;
        As[lc+0][rA1] = a1.x; As[lc+1][rA1] = a1.y; As[lc+2][rA1] = a1.z; As[lc+3][rA1] = a1.w;
        Bs[lc+0][lr]      = b0.x; Bs[lc+1][lr]      = b0.y; Bs[lc+2][lr]      = b0.z; Bs[lc+3][lr]      = b0.w;
        Bs[lc+0][64 + lr] = b1.x; Bs[lc+1][64 + lr] = b1.y; Bs[lc+2][64 + lr] = b1.z; Bs[lc+3][64 + lr] = b1.w;
        __syncthreads();

        #pragma unroll
        for (int kk = 0; kk < 16; kk++) {
            float4 av0 = *(const float4*)&As[kk][tm * 8];
            float4 av1 = *(const float4*)&As[kk][tm * 8 + 4];
            float4 bu  = *(const float4*)&Bs[kk][tn * 4];
            float4 bg  = *(const float4*)&Bs[kk][64 + tn * 4];
            float a[8] = {av0.x, av0.y, av0.z, av0.w, av1.x, av1.y, av1.z, av1.w};
            float u[4] = {bu.x, bu.y, bu.z, bu.w};
            float g[4] = {bg.x, bg.y, bg.z, bg.w};
            #pragma unroll
            for (int i = 0; i < 8; i++)
                #pragma unroll
                for (int j = 0; j < 4; j++) {
                    acc_u[i][j] += a[i] * u[j];
                    acc_g[i][j] += a[i] * g[j];
                }
        }
    }

    #pragma unroll
    for (int i = 0; i < 8; i++) {
        int m = m0 + tm * 8 + i;
        if (m < Me) {
            float* out = g_act + (size_t)(base + m) * H_DIM + j0 + tn * 4;
            #pragma unroll
            for (int j = 0; j < 4; j++) {
                float gv = acc_g[i][j];
                float s  = gv / (1.f + __expf(-gv));   // silu
                out[j] = acc_u[i][j] * s;
            }
        }
    }
}

// ---------------- fc2 + weighted scatter-add ----------------
__global__ __launch_bounds__(256) void fc2_scatter_kernel(const float* __restrict__ W2,
                                                          float* __restrict__ y) {
    int e  = blockIdx.z;
    int Me = g_counts[e];
    int m0 = blockIdx.x * 128;
    if (m0 >= Me) return;
    int base = g_offsets[e];
    int n0   = blockIdx.y * 128;
    const float* W2e = W2 + (size_t)e * D_DIM * H_DIM;

    __shared__ float As[16][132];
    __shared__ float Bs[16][132];

    int tid = threadIdx.x;
    int tm = tid >> 4, tn = tid & 15;
    int lr = tid >> 2;
    int lc = (tid & 3) * 4;

    int rA0 = lr, rA1 = lr + 64;
    const float* ap0 = (m0 + rA0 < Me) ? g_act + (size_t)(base + m0 + rA0) * H_DIM + lc : nullptr;
    const float* ap1 = (m0 + rA1 < Me) ? g_act + (size_t)(base + m0 + rA1) * H_DIM + lc : nullptr;
    const float* bp0 = W2e + (size_t)(n0 + lr) * H_DIM + lc;
    const float* bp1 = W2e + (size_t)(n0 + 64 + lr) * H_DIM + lc;

    float acc[8][8];
    #pragma unroll
    for (int i = 0; i < 8; i++)
        #pragma unroll
        for (int j = 0; j < 8; j++) acc[i][j] = 0.f;

    for (int k0 = 0; k0 < H_DIM; k0 += 16) {
        float4 a0 = ap0 ? *(const float4*)(ap0 + k0) : make_float4(0,0,0,0);
        float4 a1 = ap1 ? *(const float4*)(ap1 + k0) : make_float4(0,0,0,0);
        float4 b0 = *(const float4*)(bp0 + k0);
        float4 b1 = *(const float4*)(bp1 + k0);
        __syncthreads();
        As[lc+0][rA0] = a0.x; As[lc+1][rA0] = a0.y; As[lc+2][rA0] = a0.z; As[lc+3][rA0] = a0.w;
        As[lc+0][rA1] = a1.x; As[lc+1][rA1] = a1.y; As[lc+2][rA1] = a1.z; As[lc+3][rA1] = a1.w;
        Bs[lc+0][lr]      = b0.x; Bs[lc+1][lr]      = b0.y; Bs[lc+2][lr]      = b0.z; Bs[lc+3][lr]      = b0.w;
        Bs[lc+0][64 + lr] = b1.x; Bs[lc+1][64 + lr] = b1.y; Bs[lc+2][64 + lr] = b1.z; Bs[lc+3][64 + lr] = b1.w;
        __syncthreads();

        #pragma unroll
        for (int kk = 0; kk < 16; kk++) {
            float4 av0 = *(const float4*)&As[kk][tm * 8];
            float4 av1 = *(const float4*)&As[kk][tm * 8 + 4];
            float4 bv0 = *(const float4*)&Bs[kk][tn * 8];
            float4 bv1 = *(const float4*)&Bs[kk][tn * 8 + 4];
            float a[8] = {av0.x, av0.y, av0.z, av0.w, av1.x, av1.y, av1.z, av1.w};
            float b[8] = {bv0.x, bv0.y, bv0.z, bv0.w, bv1.x, bv1.y, bv1.z, bv1.w};
            #pragma unroll
            for (int i = 0; i < 8; i++)
                #pragma unroll
                for (int j = 0; j < 8; j++) acc[i][j] += a[i] * b[j];
        }
    }

    #pragma unroll
    for (int i = 0; i < 8; i++) {
        int m = m0 + tm * 8 + i;
        if (m < Me) {
            int   t = g_tok[base + m];
            float w = g_gw[base + m];
            float* yr = y + (size_t)t * D_DIM + n0 + tn * 8;
            #pragma unroll
            for (int j = 0; j < 8; j++) atomicAdd(&yr[j], acc[i][j] * w);
        }
    }
}

// ---------------- launch ----------------
extern "C" void kernel_launch(void* const* d_in, const int* in_sizes, int n_in,
                              void* d_out, int out_size) {
    const float* x   = (const float*)d_in[0];        // [T, D]
    const float* w   = (const float*)d_in[1];        // [T, K]
    const void*  idx = d_in[2];                      // [T, K] int64 or int32 (detected)
    const float* W1  = (const float*)d_in[3];        // [E, 2H, D]
    const float* W2  = (const float*)d_in[4];        // [E, D, H]
    float* y = (float*)d_out;                        // [T, D]

    int n4 = T_TOK * D_DIM / 4;
    zero_y_kernel<<<(n4 + 255) / 256, 256>>>((float4*)y, n4);
    route_reset_kernel<<<1, 32>>>();
    detect_idx_kernel<<<RMAX / 256, 256>>>((const int*)idx);
    route_count_kernel<<<RMAX / 256, 256>>>(idx);
    route_scan_kernel<<<1, 1>>>();
    route_place_kernel<<<RMAX / 256, 256>>>(idx, w);

    dim3 g1(RMAX / 128, H_DIM / 64, E_EXP);   // (64, 32, 8), most blocks early-exit
    fc1_glu_kernel<<<g1, 256>>>(x, W1);

    dim3 g2(RMAX / 128, D_DIM / 128, E_EXP);  // (64, 8, 8)
    fc2_scatter_kernel<<<g2, 256>>>(W2, y);
}

// round 3
// speedup vs baseline: 2.0499x; 2.0499x over previous
#include <cuda_runtime.h>
#include <cstdint>

#define T_TOK 4096
#define D_DIM 1024
#define H_DIM 2048
#define E_EXP 8
#define K_TOP 2
#define RMAX (T_TOK * K_TOP)

// ---------------- device scratch (no allocation allowed) ----------------
__device__ int   g_counts[E_EXP];
__device__ int   g_offsets[E_EXP + 1];
__device__ int   g_cursor[E_EXP];
__device__ int   g_is64;
__device__ int   g_tok[RMAX];
__device__ float g_gw[RMAX];
__device__ float g_act[(size_t)RMAX * H_DIM];               // fc1 activations (tf32-rounded)
__device__ float g_xr[(size_t)T_TOK * D_DIM];               // x rounded to tf32
__device__ float g_w1r[(size_t)E_EXP * 2 * H_DIM * D_DIM];  // W1 rounded to tf32 (134 MB)
__device__ float g_w2r[(size_t)E_EXP * D_DIM * H_DIM];      // W2 rounded to tf32 (67 MB)

// ---------------- helpers ----------------
__device__ __forceinline__ uint32_t smem_u32(const void* p) {
    uint32_t a;
    asm("{ .reg .u64 t; cvta.to.shared.u64 t, %1; cvt.u32.u64 %0, t; }" : "=r"(a) : "l"(p));
    return a;
}
__device__ __forceinline__ uint32_t lds32(uint32_t a) {
    uint32_t v;
    asm volatile("ld.shared.b32 %0, [%1];" : "=r"(v) : "r"(a));
    return v;
}
__device__ __forceinline__ float tf32r(float x) {
    uint32_t r;
    asm("cvt.rna.tf32.f32 %0, %1;" : "=r"(r) : "f"(x));
    return __uint_as_float(r);
}
#define CP16(d, s)  asm volatile("cp.async.cg.shared.global [%0], [%1], 16;" :: "r"(d), "l"(s))
#define CPCOMMIT()  asm volatile("cp.async.commit_group;" ::: "memory")
#define CPWAIT2()   asm volatile("cp.async.wait_group 2;" ::: "memory")

#define MMA(c, a, b) \
    asm volatile("mma.sync.aligned.m16n8k8.row.col.f32.tf32.tf32.f32 " \
        "{%0,%1,%2,%3},{%4,%5,%6,%7},{%8,%9},{%0,%1,%2,%3};" \
        : "+f"((c)[0]), "+f"((c)[1]), "+f"((c)[2]), "+f"((c)[3]) \
        : "r"((a)[0]), "r"((a)[1]), "r"((a)[2]), "r"((a)[3]), "r"((b)[0]), "r"((b)[1]))

#define KC 32                        // K floats per chunk (128 B rows)
#define ASTG (128 * 128)             // 16 KB A per stage
#define BSTG (256 * 128)             // 32 KB B per stage
#define STG  (ASTG + BSTG)           // 48 KB
#define SMEMSZ (3 * STG)             // 144 KB

// ---------------- small kernels ----------------
__global__ void zero_y_kernel(float4* y4, int n4) {
    int i = blockIdx.x * blockDim.x + threadIdx.x;
    if (i < n4) y4[i] = make_float4(0.f, 0.f, 0.f, 0.f);
}
__global__ void round_to_kernel(const float4* __restrict__ src, float4* __restrict__ dst) {
    int i = blockIdx.x * 256 + threadIdx.x;
    float4 v = src[i];
    dst[i] = make_float4(tf32r(v.x), tf32r(v.y), tf32r(v.z), tf32r(v.w));
}
__global__ void route_reset_kernel() {
    int t = threadIdx.x;
    if (t < E_EXP) { g_counts[t] = 0; g_cursor[t] = 0; }
    if (t == 0) g_is64 = 1;
}
__global__ void detect_idx_kernel(const int* __restrict__ idx32) {
    int i = blockIdx.x * 256 + threadIdx.x;
    if (i < RMAX && (i & 1) && idx32[i] != 0) g_is64 = 0;
}
__device__ __forceinline__ int load_expert(const void* idxp, int i) {
    if (g_is64) return (int)((const long long*)idxp)[i];
    return ((const int*)idxp)[i];
}
__global__ void route_count_kernel(const void* __restrict__ idxp) {
    int i = blockIdx.x * 256 + threadIdx.x;
    if (i < RMAX) atomicAdd(&g_counts[load_expert(idxp, i)], 1);
}
__global__ void route_scan_kernel() {
    int s = 0;
    for (int e = 0; e < E_EXP; e++) { g_offsets[e] = s; s += g_counts[e]; }
    g_offsets[E_EXP] = s;
}
__global__ void route_place_kernel(const void* __restrict__ idxp,
                                   const float* __restrict__ w) {
    int i = blockIdx.x * 256 + threadIdx.x;
    if (i < RMAX) {
        int e = load_expert(idxp, i);
        int p = atomicAdd(&g_cursor[e], 1);
        int slot = g_offsets[e] + p;
        g_tok[slot] = i / K_TOP;
        g_gw[slot]  = w[i];
    }
}

// ================= fc1: gathered [Me x 1024] x W1^T, fused SwiGLU =================
// Block tile 128(M) x 256(N); N = 128 u-rows + 128 gate-rows interleaved per
// warp group so each warp holds matching u/gate accumulators.
__global__ __launch_bounds__(256, 1) void fc1_mma() {
    int e  = blockIdx.z, Me = g_counts[e];
    int m0 = blockIdx.x * 128;
    if (m0 >= Me) return;
    int base = g_offsets[e];
    int hb   = blockIdx.y * 128;     // 128 h-cols per block

    extern __shared__ char smem[];
    uint32_t sb = smem_u32(smem);
    int tid = threadIdx.x, lane = tid & 31, wid = tid >> 5;
    int wm = wid & 1, wn = wid >> 1;
    uint32_t qr = lane >> 2, qc = lane & 3;

    // --- loader setup ---
    int arow = tid >> 1;
    int mrow = m0 + arow; if (mrow > Me - 1) mrow = Me - 1;
    const float* agp = g_xr + (size_t)g_tok[base + mrow] * D_DIM + (tid & 1) * 16;
    uint32_t adst[4];
#pragma unroll
    for (int j = 0; j < 4; j++) {
        int cc = (tid & 1) * 4 + j;
        adst[j] = arow * 128 + ((cc * 16) ^ ((arow & 7) << 4));
    }
    int brow = tid;                       // 0..255
    int w4 = brow >> 6, s4 = brow & 63;
    int grow = (s4 < 32) ? (hb + w4 * 32 + s4) : (H_DIM + hb + w4 * 32 + (s4 - 32));
    const float* bgp = g_w1r + (size_t)e * 2 * H_DIM * D_DIM + (size_t)grow * D_DIM;
    uint32_t bdst[8];
#pragma unroll
    for (int j = 0; j < 8; j++)
        bdst[j] = ASTG + brow * 128 + ((j * 16) ^ ((brow & 7) << 4));

#define LOADST(c, st) do { \
        uint32_t so = sb + (st) * STG; \
        const float* a_ = agp + (c) * KC; \
        const float* b_ = bgp + (c) * KC; \
        _Pragma("unroll") for (int j = 0; j < 4; j++) CP16(so + adst[j], a_ + j * 4); \
        _Pragma("unroll") for (int j = 0; j < 8; j++) CP16(so + bdst[j], b_ + j * 4); \
    } while (0)

    float acc[4][8][4];
#pragma unroll
    for (int i = 0; i < 4; i++)
#pragma unroll
        for (int j = 0; j < 8; j++)
#pragma unroll
            for (int k = 0; k < 4; k++) acc[i][j][k] = 0.f;

    const int NC = D_DIM / KC;  // 32
    LOADST(0, 0); CPCOMMIT();
    LOADST(1, 1); CPCOMMIT();

    for (int c = 0; c < NC; c++) {
        if (c > 0) __syncthreads();               // WAR: compute(c-1) done before refill
        int cn = c + 2;
        if (cn < NC) LOADST(cn, cn % 3);
        CPCOMMIT();
        CPWAIT2();
        __syncthreads();
        uint32_t Ab = sb + (c % 3) * STG;
        uint32_t Bb = Ab + ASTG;
#pragma unroll
        for (int ks = 0; ks < 4; ks++) {
            uint32_t kx0 = (uint32_t)(ks * 32 + qc * 4) ^ (qr << 4);
            uint32_t kx1 = kx0 ^ 16;
            uint32_t Af[4][4], Bf[8][2];
#pragma unroll
            for (int mi = 0; mi < 4; mi++) {
                uint32_t r0 = Ab + (uint32_t)(wm * 64 + mi * 16 + qr) * 128;
                Af[mi][0] = lds32(r0 + kx0);
                Af[mi][1] = lds32(r0 + 1024 + kx0);
                Af[mi][2] = lds32(r0 + kx1);
                Af[mi][3] = lds32(r0 + 1024 + kx1);
            }
#pragma unroll
            for (int ni = 0; ni < 8; ni++) {
                uint32_t rn = Bb + (uint32_t)(wn * 64 + ni * 8 + qr) * 128;
                Bf[ni][0] = lds32(rn + kx0);
                Bf[ni][1] = lds32(rn + kx1);
            }
#pragma unroll
            for (int mi = 0; mi < 4; mi++)
#pragma unroll
                for (int ni = 0; ni < 8; ni++)
                    MMA(acc[mi][ni], Af[mi], Bf[ni]);
        }
    }
#undef LOADST

    // --- epilogue: silu(gate) * u, tf32-round, store to g_act ---
#pragma unroll
    for (int mi = 0; mi < 4; mi++) {
        int r0 = m0 + wm * 64 + mi * 16 + (int)qr;
        int r1 = r0 + 8;
#pragma unroll
        for (int ni = 0; ni < 4; ni++) {
            float* u = acc[mi][ni];
            float* g = acc[mi][ni + 4];
            int hcol = hb + wn * 32 + ni * 8 + (int)qc * 2;
            if (r0 < Me) {
                float g0 = g[0], g1 = g[1];
                float v0 = tf32r(u[0] * (g0 / (1.f + __expf(-g0))));
                float v1 = tf32r(u[1] * (g1 / (1.f + __expf(-g1))));
                *(float2*)(g_act + (size_t)(base + r0) * H_DIM + hcol) = make_float2(v0, v1);
            }
            if (r1 < Me) {
                float g2 = g[2], g3 = g[3];
                float v2 = tf32r(u[2] * (g2 / (1.f + __expf(-g2))));
                float v3 = tf32r(u[3] * (g3 / (1.f + __expf(-g3))));
                *(float2*)(g_act + (size_t)(base + r1) * H_DIM + hcol) = make_float2(v2, v3);
            }
        }
    }
}

// ================= fc2: [Me x 2048] x W2^T, weighted scatter-add =================
__global__ __launch_bounds__(256, 1) void fc2_mma(float* __restrict__ y) {
    int e  = blockIdx.z, Me = g_counts[e];
    int m0 = blockIdx.x * 128;
    if (m0 >= Me) return;
    int base = g_offsets[e];
    int n0   = blockIdx.y * 256;

    extern __shared__ char smem[];
    uint32_t sb = smem_u32(smem);
    int tid = threadIdx.x, lane = tid & 31, wid = tid >> 5;
    int wm = wid & 1, wn = wid >> 1;
    uint32_t qr = lane >> 2, qc = lane & 3;

    int arow = tid >> 1;
    int mrow = m0 + arow; if (mrow > Me - 1) mrow = Me - 1;
    const float* agp = g_act + (size_t)(base + mrow) * H_DIM + (tid & 1) * 16;
    uint32_t adst[4];
#pragma unroll
    for (int j = 0; j < 4; j++) {
        int cc = (tid & 1) * 4 + j;
        adst[j] = arow * 128 + ((cc * 16) ^ ((arow & 7) << 4));
    }
    int brow = tid;
    const float* bgp = g_w2r + (size_t)e * D_DIM * H_DIM + (size_t)(n0 + brow) * H_DIM;
    uint32_t bdst[8];
#pragma unroll
    for (int j = 0; j < 8; j++)
        bdst[j] = ASTG + brow * 128 + ((j * 16) ^ ((brow & 7) << 4));

#define LOADST(c, st) do { \
        uint32_t so = sb + (st) * STG; \
        const float* a_ = agp + (c) * KC; \
        const float* b_ = bgp + (c) * KC; \
        _Pragma("unroll") for (int j = 0; j < 4; j++) CP16(so + adst[j], a_ + j * 4); \
        _Pragma("unroll") for (int j = 0; j < 8; j++) CP16(so + bdst[j], b_ + j * 4); \
    } while (0)

    float acc[4][8][4];
#pragma unroll
    for (int i = 0; i < 4; i++)
#pragma unroll
        for (int j = 0; j < 8; j++)
#pragma unroll
            for (int k = 0; k < 4; k++) acc[i][j][k] = 0.f;

    const int NC = H_DIM / KC;  // 64
    LOADST(0, 0); CPCOMMIT();
    LOADST(1, 1); CPCOMMIT();

    for (int c = 0; c < NC; c++) {
        if (c > 0) __syncthreads();
        int cn = c + 2;
        if (cn < NC) LOADST(cn, cn % 3);
        CPCOMMIT();
        CPWAIT2();
        __syncthreads();
        uint32_t Ab = sb + (c % 3) * STG;
        uint32_t Bb = Ab + ASTG;
#pragma unroll
        for (int ks = 0; ks < 4; ks++) {
            uint32_t kx0 = (uint32_t)(ks * 32 + qc * 4) ^ (qr << 4);
            uint32_t kx1 = kx0 ^ 16;
            uint32_t Af[4][4], Bf[8][2];
#pragma unroll
            for (int mi = 0; mi < 4; mi++) {
                uint32_t r0 = Ab + (uint32_t)(wm * 64 + mi * 16 + qr) * 128;
                Af[mi][0] = lds32(r0 + kx0);
                Af[mi][1] = lds32(r0 + 1024 + kx0);
                Af[mi][2] = lds32(r0 + kx1);
                Af[mi][3] = lds32(r0 + 1024 + kx1);
            }
#pragma unroll
            for (int ni = 0; ni < 8; ni++) {
                uint32_t rn = Bb + (uint32_t)(wn * 64 + ni * 8 + qr) * 128;
                Bf[ni][0] = lds32(rn + kx0);
                Bf[ni][1] = lds32(rn + kx1);
            }
#pragma unroll
            for (int mi = 0; mi < 4; mi++)
#pragma unroll
                for (int ni = 0; ni < 8; ni++)
                    MMA(acc[mi][ni], Af[mi], Bf[ni]);
        }
    }
#undef LOADST

    // --- epilogue: weighted scatter-add into y ---
#pragma unroll
    for (int mi = 0; mi < 4; mi++) {
        int r0 = m0 + wm * 64 + mi * 16 + (int)qr;
        int r1 = r0 + 8;
        int   t0 = 0, t1 = 0;
        float w0 = 0.f, w1 = 0.f;
        bool v0 = (r0 < Me), v1 = (r1 < Me);
        if (v0) { t0 = g_tok[base + r0]; w0 = g_gw[base + r0]; }
        if (v1) { t1 = g_tok[base + r1]; w1 = g_gw[base + r1]; }
#pragma unroll
        for (int ni = 0; ni < 8; ni++) {
            int col = n0 + wn * 64 + ni * 8 + (int)qc * 2;
            float* c = acc[mi][ni];
            if (v0) {
                atomicAdd(y + (size_t)t0 * D_DIM + col,     c[0] * w0);
                atomicAdd(y + (size_t)t0 * D_DIM + col + 1, c[1] * w0);
            }
            if (v1) {
                atomicAdd(y + (size_t)t1 * D_DIM + col,     c[2] * w1);
                atomicAdd(y + (size_t)t1 * D_DIM + col + 1, c[3] * w1);
            }
        }
    }
}

// ---------------- launch ----------------
extern "C" void kernel_launch(void* const* d_in, const int* in_sizes, int n_in,
                              void* d_out, int out_size) {
    const float* x   = (const float*)d_in[0];
    const float* w   = (const float*)d_in[1];
    const void*  idx = d_in[2];
    const float* W1  = (const float*)d_in[3];
    const float* W2  = (const float*)d_in[4];
    float* y = (float*)d_out;

    cudaFuncSetAttribute(fc1_mma, cudaFuncAttributeMaxDynamicSharedMemorySize, SMEMSZ);
    cudaFuncSetAttribute(fc2_mma, cudaFuncAttributeMaxDynamicSharedMemorySize, SMEMSZ);

    float* xr_p;  cudaGetSymbolAddress((void**)&xr_p,  g_xr);
    float* w1r_p; cudaGetSymbolAddress((void**)&w1r_p, g_w1r);
    float* w2r_p; cudaGetSymbolAddress((void**)&w2r_p, g_w2r);

    int n4 = T_TOK * D_DIM / 4;
    zero_y_kernel<<<(n4 + 255) / 256, 256>>>((float4*)y, n4);
    round_to_kernel<<<n4 / 256, 256>>>((const float4*)x, (float4*)xr_p);
    int w1n4 = E_EXP * 2 * H_DIM * D_DIM / 4;
    round_to_kernel<<<w1n4 / 256, 256>>>((const float4*)W1, (float4*)w1r_p);
    int w2n4 = E_EXP * D_DIM * H_DIM / 4;
    round_to_kernel<<<w2n4 / 256, 256>>>((const float4*)W2, (float4*)w2r_p);

    route_reset_kernel<<<1, 32>>>();
    detect_idx_kernel<<<RMAX / 256, 256>>>((const int*)idx);
    route_count_kernel<<<RMAX / 256, 256>>>(idx);
    route_scan_kernel<<<1, 1>>>();
    route_place_kernel<<<RMAX / 256, 256>>>(idx, w);

    dim3 g1(RMAX / 128, H_DIM / 128, E_EXP);   // (64, 16, 8), ~1024 live blocks
    fc1_mma<<<g1, 256, SMEMSZ>>>();

    dim3 g2(RMAX / 128, D_DIM / 256, E_EXP);   // (64, 4, 8), ~256 live blocks
    fc2_mma<<<g2, 256, SMEMSZ>>>(y);
}

// round 4
// speedup vs baseline: 2.1849x; 1.0659x over previous
#include <cuda_runtime.h>
#include <cstdint>

#define T_TOK 4096
#define D_DIM 1024
#define H_DIM 2048
#define E_EXP 8
#define K_TOP 2
#define RMAX (T_TOK * K_TOP)

// ---------------- device scratch (no allocation allowed) ----------------
__device__ int   g_counts[E_EXP];
__device__ int   g_offsets[E_EXP + 1];
__device__ int   g_cursor[E_EXP];
__device__ int   g_is64;
__device__ int   g_tok[RMAX];
__device__ float g_gw[RMAX];
__device__ float g_act[(size_t)RMAX * H_DIM];               // fc1 activations (tf32-rounded)
__device__ float g_xr[(size_t)T_TOK * D_DIM];               // x rounded to tf32
__device__ float g_w1r[(size_t)E_EXP * 2 * H_DIM * D_DIM];  // W1 rounded to tf32
__device__ float g_w2r[(size_t)E_EXP * D_DIM * H_DIM];      // W2 rounded to tf32

// ---------------- helpers ----------------
__device__ __forceinline__ uint32_t smem_u32(const void* p) {
    uint32_t a;
    asm("{ .reg .u64 t; cvta.to.shared.u64 t, %1; cvt.u32.u64 %0, t; }" : "=r"(a) : "l"(p));
    return a;
}
__device__ __forceinline__ float tf32r(float x) {
    uint32_t r;
    asm("cvt.rna.tf32.f32 %0, %1;" : "=r"(r) : "f"(x));
    return __uint_as_float(r);
}
__device__ __forceinline__ void ldm_x4(uint32_t (&r)[4], uint32_t addr) {
    asm volatile("ldmatrix.sync.aligned.m8n8.x4.shared.b16 {%0,%1,%2,%3}, [%4];"
        : "=r"(r[0]), "=r"(r[1]), "=r"(r[2]), "=r"(r[3]) : "r"(addr));
}
#define CP16(d, s)  asm volatile("cp.async.cg.shared.global [%0], [%1], 16;" :: "r"(d), "l"(s))
#define CPCOMMIT()  asm volatile("cp.async.commit_group;" ::: "memory")
#define CPWAIT2()   asm volatile("cp.async.wait_group 2;" ::: "memory")

#define MMA(c, a, b0, b1) \
    asm volatile("mma.sync.aligned.m16n8k8.row.col.f32.tf32.tf32.f32 " \
        "{%0,%1,%2,%3},{%4,%5,%6,%7},{%8,%9},{%0,%1,%2,%3};" \
        : "+f"((c)[0]), "+f"((c)[1]), "+f"((c)[2]), "+f"((c)[3]) \
        : "r"((a)[0]), "r"((a)[1]), "r"((a)[2]), "r"((a)[3]), "r"(b0), "r"(b1))

#define KC 32                        // K floats per chunk (128 B rows)
#define ASTG (128 * 128)             // 16 KB A per stage
#define BSTG (256 * 128)             // 32 KB B per stage
#define STG  (ASTG + BSTG)           // 48 KB
#define NSTG 4
#define SMEMSZ (NSTG * STG)          // 192 KB

// ---------------- small kernels ----------------
__global__ void zero_y_kernel(float4* y4, int n4) {
    int i = blockIdx.x * blockDim.x + threadIdx.x;
    if (i < n4) y4[i] = make_float4(0.f, 0.f, 0.f, 0.f);
}
__global__ void round_to_kernel(const float4* __restrict__ src, float4* __restrict__ dst) {
    int i = blockIdx.x * 256 + threadIdx.x;
    float4 v = src[i];
    dst[i] = make_float4(tf32r(v.x), tf32r(v.y), tf32r(v.z), tf32r(v.w));
}
__global__ void route_reset_kernel() {
    int t = threadIdx.x;
    if (t < E_EXP) { g_counts[t] = 0; g_cursor[t] = 0; }
    if (t == 0) g_is64 = 1;
}
__global__ void detect_idx_kernel(const int* __restrict__ idx32) {
    int i = blockIdx.x * 256 + threadIdx.x;
    if (i < RMAX && (i & 1) && idx32[i] != 0) g_is64 = 0;
}
__device__ __forceinline__ int load_expert(const void* idxp, int i) {
    if (g_is64) return (int)((const long long*)idxp)[i];
    return ((const int*)idxp)[i];
}
__global__ void route_count_kernel(const void* __restrict__ idxp) {
    int i = blockIdx.x * 256 + threadIdx.x;
    if (i < RMAX) atomicAdd(&g_counts[load_expert(idxp, i)], 1);
}
__global__ void route_scan_kernel() {
    int s = 0;
    for (int e = 0; e < E_EXP; e++) { g_offsets[e] = s; s += g_counts[e]; }
    g_offsets[E_EXP] = s;
}
__global__ void route_place_kernel(const void* __restrict__ idxp,
                                   const float* __restrict__ w) {
    int i = blockIdx.x * 256 + threadIdx.x;
    if (i < RMAX) {
        int e = load_expert(idxp, i);
        int p = atomicAdd(&g_cursor[e], 1);
        int slot = g_offsets[e] + p;
        g_tok[slot] = i / K_TOP;
        g_gw[slot]  = w[i];
    }
}

// ---------------- shared mainloop (ldmatrix + 4-stage cp.async) ----------------
// acc[4][8][4]: warp computes 64(M) x 64(N). Fragment addressing:
// A: 4 ldmatrix.x4 per ks (m16 x k8 each); B: 4 ldmatrix.x4 per ks (n16 x k8 each).
struct Frag { uint32_t aRow[4]; uint32_t bRow[4]; uint32_t kA[4]; uint32_t kB[4]; };

__device__ __forceinline__ void frag_setup(Frag& f, int lane, int wm, int wn) {
    int lane7 = lane & 7, lg = lane >> 3;
    uint32_t swz = (uint32_t)lane7 << 4;
#pragma unroll
    for (int mi = 0; mi < 4; mi++)
        f.aRow[mi] = (uint32_t)(wm * 64 + mi * 16 + lane7 + ((lg & 1) << 3)) * 128;
#pragma unroll
    for (int nj = 0; nj < 4; nj++)
        f.bRow[nj] = ASTG + (uint32_t)(wn * 64 + nj * 16 + lane7 + ((lg >> 1) << 3)) * 128;
#pragma unroll
    for (int ks = 0; ks < 4; ks++) {
        f.kA[ks] = ((uint32_t)(ks * 32) + (((uint32_t)lg >> 1) << 4)) ^ swz;
        f.kB[ks] = ((uint32_t)(ks * 32) + (((uint32_t)lg & 1) << 4)) ^ swz;
    }
}

__device__ __forceinline__ void chunk_mma(float (&acc)[4][8][4], const Frag& f, uint32_t Ab) {
#pragma unroll
    for (int ks = 0; ks < 4; ks++) {
        uint32_t Af[4][4], Bq[4][4];
#pragma unroll
        for (int mi = 0; mi < 4; mi++) ldm_x4(Af[mi], Ab + f.aRow[mi] + f.kA[ks]);
#pragma unroll
        for (int nj = 0; nj < 4; nj++) ldm_x4(Bq[nj], Ab + f.bRow[nj] + f.kB[ks]);
#pragma unroll
        for (int mi = 0; mi < 4; mi++)
#pragma unroll
            for (int ni = 0; ni < 8; ni++) {
                const uint32_t* bq = Bq[ni >> 1] + ((ni & 1) << 1);
                MMA(acc[mi][ni], Af[mi], bq[0], bq[1]);
            }
    }
}

// ================= fc1: gathered [Me x 1024] x W1^T, fused SwiGLU =================
__global__ __launch_bounds__(256, 1) void fc1_mma() {
    int e  = blockIdx.z, Me = g_counts[e];
    int m0 = blockIdx.x * 128;
    if (m0 >= Me) return;
    int base = g_offsets[e];
    int hb   = blockIdx.y * 128;

    extern __shared__ char smem[];
    uint32_t sb = smem_u32(smem);
    int tid = threadIdx.x, lane = tid & 31, wid = tid >> 5;
    int wm = wid & 1, wn = wid >> 1;
    uint32_t qr = lane >> 2, qc = lane & 3;

    // loaders
    int arow = tid >> 1;
    int mrow = m0 + arow; if (mrow > Me - 1) mrow = Me - 1;
    const float* agp = g_xr + (size_t)g_tok[base + mrow] * D_DIM + (tid & 1) * 16;
    uint32_t adst[4];
#pragma unroll
    for (int j = 0; j < 4; j++) {
        int cc = (tid & 1) * 4 + j;
        adst[j] = arow * 128 + ((cc * 16) ^ ((arow & 7) << 4));
    }
    int brow = tid;
    int w4 = brow >> 6, s4 = brow & 63;
    int grow = (s4 < 32) ? (hb + w4 * 32 + s4) : (H_DIM + hb + w4 * 32 + (s4 - 32));
    const float* bgp = g_w1r + (size_t)e * 2 * H_DIM * D_DIM + (size_t)grow * D_DIM;
    uint32_t bdst[8];
#pragma unroll
    for (int j = 0; j < 8; j++)
        bdst[j] = ASTG + brow * 128 + ((j * 16) ^ ((brow & 7) << 4));

#define LOADST(c, st) do { \
        uint32_t so = sb + (st) * STG; \
        const float* a_ = agp + (c) * KC; \
        const float* b_ = bgp + (c) * KC; \
        _Pragma("unroll") for (int j = 0; j < 4; j++) CP16(so + adst[j], a_ + j * 4); \
        _Pragma("unroll") for (int j = 0; j < 8; j++) CP16(so + bdst[j], b_ + j * 4); \
    } while (0)

    float acc[4][8][4];
#pragma unroll
    for (int i = 0; i < 4; i++)
#pragma unroll
        for (int j = 0; j < 8; j++)
#pragma unroll
            for (int k = 0; k < 4; k++) acc[i][j][k] = 0.f;

    Frag f; frag_setup(f, lane, wm, wn);

    const int NC = D_DIM / KC;  // 32
    LOADST(0, 0); CPCOMMIT();
    LOADST(1, 1); CPCOMMIT();
    LOADST(2, 2); CPCOMMIT();

    for (int c = 0; c < NC; c++) {
        CPWAIT2();
        __syncthreads();
        int cn = c + 3;
        if (cn < NC) LOADST(cn, cn & 3);
        CPCOMMIT();
        chunk_mma(acc, f, sb + (c & 3) * STG);
    }
#undef LOADST

    // epilogue: silu(gate) * u, tf32-round, store to g_act
#pragma unroll
    for (int mi = 0; mi < 4; mi++) {
        int r0 = m0 + wm * 64 + mi * 16 + (int)qr;
        int r1 = r0 + 8;
#pragma unroll
        for (int ni = 0; ni < 4; ni++) {
            float* u = acc[mi][ni];
            float* g = acc[mi][ni + 4];
            int hcol = hb + wn * 32 + ni * 8 + (int)qc * 2;
            if (r0 < Me) {
                float g0 = g[0], g1 = g[1];
                float v0 = tf32r(u[0] * (g0 / (1.f + __expf(-g0))));
                float v1 = tf32r(u[1] * (g1 / (1.f + __expf(-g1))));
                *(float2*)(g_act + (size_t)(base + r0) * H_DIM + hcol) = make_float2(v0, v1);
            }
            if (r1 < Me) {
                float g2 = g[2], g3 = g[3];
                float v2 = tf32r(u[2] * (g2 / (1.f + __expf(-g2))));
                float v3 = tf32r(u[3] * (g3 / (1.f + __expf(-g3))));
                *(float2*)(g_act + (size_t)(base + r1) * H_DIM + hcol) = make_float2(v2, v3);
            }
        }
    }
}

// ================= fc2: [Me x 2048] x W2^T, weighted scatter-add =================
__global__ __launch_bounds__(256, 1) void fc2_mma(float* __restrict__ y) {
    int e  = blockIdx.z, Me = g_counts[e];
    int m0 = blockIdx.x * 128;
    if (m0 >= Me) return;
    int base = g_offsets[e];
    int n0   = blockIdx.y * 256;

    extern __shared__ char smem[];
    uint32_t sb = smem_u32(smem);
    int tid = threadIdx.x, lane = tid & 31, wid = tid >> 5;
    int wm = wid & 1, wn = wid >> 1;
    uint32_t qr = lane >> 2, qc = lane & 3;

    int arow = tid >> 1;
    int mrow = m0 + arow; if (mrow > Me - 1) mrow = Me - 1;
    const float* agp = g_act + (size_t)(base + mrow) * H_DIM + (tid & 1) * 16;
    uint32_t adst[4];
#pragma unroll
    for (int j = 0; j < 4; j++) {
        int cc = (tid & 1) * 4 + j;
        adst[j] = arow * 128 + ((cc * 16) ^ ((arow & 7) << 4));
    }
    int brow = tid;
    const float* bgp = g_w2r + (size_t)e * D_DIM * H_DIM + (size_t)(n0 + brow) * H_DIM;
    uint32_t bdst[8];
#pragma unroll
    for (int j = 0; j < 8; j++)
        bdst[j] = ASTG + brow * 128 + ((j * 16) ^ ((brow & 7) << 4));

#define LOADST(c, st) do { \
        uint32_t so = sb + (st) * STG; \
        const float* a_ = agp + (c) * KC; \
        const float* b_ = bgp + (c) * KC; \
        _Pragma("unroll") for (int j = 0; j < 4; j++) CP16(so + adst[j], a_ + j * 4); \
        _Pragma("unroll") for (int j = 0; j < 8; j++) CP16(so + bdst[j], b_ + j * 4); \
    } while (0)

    float acc[4][8][4];
#pragma unroll
    for (int i = 0; i < 4; i++)
#pragma unroll
        for (int j = 0; j < 8; j++)
#pragma unroll
            for (int k = 0; k < 4; k++) acc[i][j][k] = 0.f;

    Frag f; frag_setup(f, lane, wm, wn);

    const int NC = H_DIM / KC;  // 64
    LOADST(0, 0); CPCOMMIT();
    LOADST(1, 1); CPCOMMIT();
    LOADST(2, 2); CPCOMMIT();

    for (int c = 0; c < NC; c++) {
        CPWAIT2();
        __syncthreads();
        int cn = c + 3;
        if (cn < NC) LOADST(cn, cn & 3);
        CPCOMMIT();
        chunk_mma(acc, f, sb + (c & 3) * STG);
    }
#undef LOADST

    // epilogue: weighted scatter-add into y
#pragma unroll
    for (int mi = 0; mi < 4; mi++) {
        int r0 = m0 + wm * 64 + mi * 16 + (int)qr;
        int r1 = r0 + 8;
        int   t0 = 0, t1 = 0;
        float w0 = 0.f, w1 = 0.f;
        bool v0 = (r0 < Me), v1 = (r1 < Me);
        if (v0) { t0 = g_tok[base + r0]; w0 = g_gw[base + r0]; }
        if (v1) { t1 = g_tok[base + r1]; w1 = g_gw[base + r1]; }
#pragma unroll
        for (int ni = 0; ni < 8; ni++) {
            int col = n0 + wn * 64 + ni * 8 + (int)qc * 2;
            float* c = acc[mi][ni];
            if (v0) {
                atomicAdd(y + (size_t)t0 * D_DIM + col,     c[0] * w0);
                atomicAdd(y + (size_t)t0 * D_DIM + col + 1, c[1] * w0);
            }
            if (v1) {
                atomicAdd(y + (size_t)t1 * D_DIM + col,     c[2] * w1);
                atomicAdd(y + (size_t)t1 * D_DIM + col + 1, c[3] * w1);
            }
        }
    }
}

// ---------------- launch ----------------
extern "C" void kernel_launch(void* const* d_in, const int* in_sizes, int n_in,
                              void* d_out, int out_size) {
    const float* x   = (const float*)d_in[0];
    const float* w   = (const float*)d_in[1];
    const void*  idx = d_in[2];
    const float* W1  = (const float*)d_in[3];
    const float* W2  = (const float*)d_in[4];
    float* y = (float*)d_out;

    cudaFuncSetAttribute(fc1_mma, cudaFuncAttributeMaxDynamicSharedMemorySize, SMEMSZ);
    cudaFuncSetAttribute(fc2_mma, cudaFuncAttributeMaxDynamicSharedMemorySize, SMEMSZ);

    float* xr_p;  cudaGetSymbolAddress((void**)&xr_p,  g_xr);
    float* w1r_p; cudaGetSymbolAddress((void**)&w1r_p, g_w1r);
    float* w2r_p; cudaGetSymbolAddress((void**)&w2r_p, g_w2r);

    int n4 = T_TOK * D_DIM / 4;
    zero_y_kernel<<<(n4 + 255) / 256, 256>>>((float4*)y, n4);
    round_to_kernel<<<n4 / 256, 256>>>((const float4*)x, (float4*)xr_p);
    int w1n4 = E_EXP * 2 * H_DIM * D_DIM / 4;
    round_to_kernel<<<w1n4 / 256, 256>>>((const float4*)W1, (float4*)w1r_p);
    int w2n4 = E_EXP * D_DIM * H_DIM / 4;
    round_to_kernel<<<w2n4 / 256, 256>>>((const float4*)W2, (float4*)w2r_p);

    route_reset_kernel<<<1, 32>>>();
    detect_idx_kernel<<<RMAX / 256, 256>>>((const int*)idx);
    route_count_kernel<<<RMAX / 256, 256>>>(idx);
    route_scan_kernel<<<1, 1>>>();
    route_place_kernel<<<RMAX / 256, 256>>>(idx, w);

    dim3 g1(RMAX / 128, H_DIM / 128, E_EXP);   // (64, 16, 8)
    fc1_mma<<<g1, 256, SMEMSZ>>>();

    dim3 g2(RMAX / 128, D_DIM / 256, E_EXP);   // (64, 4, 8)
    fc2_mma<<<g2, 256, SMEMSZ>>>(y);
}

// round 5
// speedup vs baseline: 3.9235x; 1.7957x over previous
#include <cuda_runtime.h>
#include <cuda_fp16.h>
#include <cstdint>

#define T_TOK 4096
#define D_DIM 1024
#define H_DIM 2048
#define E_EXP 8
#define K_TOP 2
#define RMAX (T_TOK * K_TOP)

// ---------------- device scratch (no allocation allowed) ----------------
__device__ int    g_counts[E_EXP];
__device__ int    g_offsets[E_EXP + 1];
__device__ int    g_tok[RMAX];
__device__ float  g_gw[RMAX];
__device__ __half g_acth[(size_t)RMAX * H_DIM];               // fc1 activations, fp16
__device__ __half g_xh[(size_t)T_TOK * D_DIM];                // x in fp16
__device__ __half g_w1h[(size_t)E_EXP * 2 * H_DIM * D_DIM];   // W1 fp16 (67 MB)
__device__ __half g_w2h[(size_t)E_EXP * D_DIM * H_DIM];       // W2 fp16 (33 MB)

// ---------------- helpers ----------------
__device__ __forceinline__ uint32_t smem_u32(const void* p) {
    uint32_t a;
    asm("{ .reg .u64 t; cvta.to.shared.u64 t, %1; cvt.u32.u64 %0, t; }" : "=r"(a) : "l"(p));
    return a;
}
__device__ __forceinline__ void ldm_x4(uint32_t (&r)[4], uint32_t addr) {
    asm volatile("ldmatrix.sync.aligned.m8n8.x4.shared.b16 {%0,%1,%2,%3}, [%4];"
        : "=r"(r[0]), "=r"(r[1]), "=r"(r[2]), "=r"(r[3]) : "r"(addr));
}
#define CP16(d, s)  asm volatile("cp.async.cg.shared.global [%0], [%1], 16;" :: "r"(d), "l"(s))
#define CPCOMMIT()  asm volatile("cp.async.commit_group;" ::: "memory")
#define CPWAIT2()   asm volatile("cp.async.wait_group 2;" ::: "memory")

// fp16 MMA, fp32 accum: per-instruction K=16
#define MMA16(c, a, b0, b1) \
    asm volatile("mma.sync.aligned.m16n8k16.row.col.f32.f16.f16.f32 " \
        "{%0,%1,%2,%3},{%4,%5,%6,%7},{%8,%9},{%0,%1,%2,%3};" \
        : "+f"((c)[0]), "+f"((c)[1]), "+f"((c)[2]), "+f"((c)[3]) \
        : "r"((a)[0]), "r"((a)[1]), "r"((a)[2]), "r"((a)[3]), "r"(b0), "r"(b1))

#define KC 64                        // K halves per chunk (128 B rows)
#define ASTG (128 * 128)             // 16 KB A per stage
#define BSTG (256 * 128)             // 32 KB B per stage
#define STG  (ASTG + BSTG)           // 48 KB
#define NSTG 4
#define SMEMSZ (NSTG * STG)          // 192 KB

// ---------------- small kernels ----------------
__global__ void zero_y_kernel(float4* y4, int n4) {
    int i = blockIdx.x * blockDim.x + threadIdx.x;
    if (i < n4) y4[i] = make_float4(0.f, 0.f, 0.f, 0.f);
}
// 8 floats -> 8 halves (16 B out) per thread
__global__ void f2h_kernel(const float4* __restrict__ src, uint4* __restrict__ dst) {
    int i = blockIdx.x * 256 + threadIdx.x;
    float4 a = src[2 * i], b = src[2 * i + 1];
    __half2 h0 = __floats2half2_rn(a.x, a.y);
    __half2 h1 = __floats2half2_rn(a.z, a.w);
    __half2 h2 = __floats2half2_rn(b.x, b.y);
    __half2 h3 = __floats2half2_rn(b.z, b.w);
    uint4 o;
    o.x = *(uint32_t*)&h0; o.y = *(uint32_t*)&h1;
    o.z = *(uint32_t*)&h2; o.w = *(uint32_t*)&h3;
    dst[i] = o;
}
// all routing in ONE kernel (single block) so fc1 is the 6th launch (ncu window)
__global__ void route_fused(const void* __restrict__ idxp, const float* __restrict__ w) {
    __shared__ int cnt[E_EXP], off[E_EXP], cur[E_EXP];
    __shared__ int is64s;
    int t = threadIdx.x;
    if (t < E_EXP) { cnt[t] = 0; cur[t] = 0; }
    if (t == 0) is64s = 1;
    __syncthreads();
    const int* i32 = (const int*)idxp;
    for (int i = t; i < RMAX; i += 256)
        if ((i & 1) && i32[i] != 0) is64s = 0;
    __syncthreads();
    int is64 = is64s;
    for (int i = t; i < RMAX; i += 256) {
        int e = is64 ? (int)((const long long*)idxp)[i] : i32[i];
        atomicAdd(&cnt[e], 1);
    }
    __syncthreads();
    if (t == 0) {
        int s = 0;
        for (int e = 0; e < E_EXP; e++) {
            off[e] = s; g_offsets[e] = s; g_counts[e] = cnt[e]; s += cnt[e];
        }
        g_offsets[E_EXP] = s;
    }
    __syncthreads();
    for (int i = t; i < RMAX; i += 256) {
        int e = is64 ? (int)((const long long*)idxp)[i] : i32[i];
        int p = atomicAdd(&cur[e], 1);
        int slot = off[e] + p;
        g_tok[slot] = i / K_TOP;
        g_gw[slot]  = w[i];
    }
}

// ---------------- shared mainloop fragments ----------------
// Warp computes 64(M) x 64(N). Per k16-slice: 4 A ldmatrix.x4 + 4 B ldmatrix.x4,
// 32 MMA16. 16 B smem chunk = k8 halves; addressing identical to tf32 version.
struct Frag { uint32_t aRow[4]; uint32_t bRow[4]; uint32_t kA[4]; uint32_t kB[4]; };

__device__ __forceinline__ void frag_setup(Frag& f, int lane, int wm, int wn) {
    int lane7 = lane & 7, lg = lane >> 3;
    uint32_t swz = (uint32_t)lane7 << 4;
#pragma unroll
    for (int mi = 0; mi < 4; mi++)
        f.aRow[mi] = (uint32_t)(wm * 64 + mi * 16 + lane7 + ((lg & 1) << 3)) * 128;
#pragma unroll
    for (int nj = 0; nj < 4; nj++)
        f.bRow[nj] = ASTG + (uint32_t)(wn * 64 + nj * 16 + lane7 + ((lg >> 1) << 3)) * 128;
#pragma unroll
    for (int ks = 0; ks < 4; ks++) {
        f.kA[ks] = ((uint32_t)(ks * 32) + (((uint32_t)lg >> 1) << 4)) ^ swz;
        f.kB[ks] = ((uint32_t)(ks * 32) + (((uint32_t)lg & 1) << 4)) ^ swz;
    }
}

__device__ __forceinline__ void chunk_mma(float (&acc)[4][8][4], const Frag& f, uint32_t Ab) {
#pragma unroll
    for (int ks = 0; ks < 4; ks++) {   // 4 x k16 = 64 halves
        uint32_t Af[4][4], Bq[4][4];
#pragma unroll
        for (int mi = 0; mi < 4; mi++) ldm_x4(Af[mi], Ab + f.aRow[mi] + f.kA[ks]);
#pragma unroll
        for (int nj = 0; nj < 4; nj++) ldm_x4(Bq[nj], Ab + f.bRow[nj] + f.kB[ks]);
#pragma unroll
        for (int mi = 0; mi < 4; mi++)
#pragma unroll
            for (int ni = 0; ni < 8; ni++) {
                const uint32_t* bq = Bq[ni >> 1] + ((ni & 1) << 1);
                MMA16(acc[mi][ni], Af[mi], bq[0], bq[1]);
            }
    }
}

// ================= fc1: gathered [Me x 1024] x W1^T, fused SwiGLU =================
__global__ __launch_bounds__(256, 1) void fc1_mma() {
    int e  = blockIdx.z, Me = g_counts[e];
    int m0 = blockIdx.x * 128;
    if (m0 >= Me) return;
    int base = g_offsets[e];
    int hb   = blockIdx.y * 128;

    extern __shared__ char smem[];
    uint32_t sb = smem_u32(smem);
    int tid = threadIdx.x, lane = tid & 31, wid = tid >> 5;
    int wm = wid & 1, wn = wid >> 1;
    uint32_t qr = lane >> 2, qc = lane & 3;

    // A loader: 2 threads per row, 4x16B each (row = 64 halves = 128 B)
    int arow = tid >> 1;
    int mrow = m0 + arow; if (mrow > Me - 1) mrow = Me - 1;
    const __half* agp = g_xh + (size_t)g_tok[base + mrow] * D_DIM + (tid & 1) * 32;
    uint32_t adst[4];
#pragma unroll
    for (int j = 0; j < 4; j++) {
        int cc = (tid & 1) * 4 + j;
        adst[j] = arow * 128 + ((cc * 16) ^ ((arow & 7) << 4));
    }
    // B loader: 1 thread per row (128 u + 128 gate), 8x16B
    int brow = tid;
    int w4 = brow >> 6, s4 = brow & 63;
    int grow = (s4 < 32) ? (hb + w4 * 32 + s4) : (H_DIM + hb + w4 * 32 + (s4 - 32));
    const __half* bgp = g_w1h + (size_t)e * 2 * H_DIM * D_DIM + (size_t)grow * D_DIM;
    uint32_t bdst[8];
#pragma unroll
    for (int j = 0; j < 8; j++)
        bdst[j] = ASTG + brow * 128 + ((j * 16) ^ ((brow & 7) << 4));

#define LOADST(c, st) do { \
        uint32_t so = sb + (st) * STG; \
        const __half* a_ = agp + (c) * KC; \
        const __half* b_ = bgp + (c) * KC; \
        _Pragma("unroll") for (int j = 0; j < 4; j++) CP16(so + adst[j], a_ + j * 8); \
        _Pragma("unroll") for (int j = 0; j < 8; j++) CP16(so + bdst[j], b_ + j * 8); \
    } while (0)

    float acc[4][8][4];
#pragma unroll
    for (int i = 0; i < 4; i++)
#pragma unroll
        for (int j = 0; j < 8; j++)
#pragma unroll
            for (int k = 0; k < 4; k++) acc[i][j][k] = 0.f;

    Frag f; frag_setup(f, lane, wm, wn);

    const int NC = D_DIM / KC;  // 16
    LOADST(0, 0); CPCOMMIT();
    LOADST(1, 1); CPCOMMIT();
    LOADST(2, 2); CPCOMMIT();

    for (int c = 0; c < NC; c++) {
        CPWAIT2();
        __syncthreads();
        int cn = c + 3;
        if (cn < NC) LOADST(cn, cn & 3);
        CPCOMMIT();
        chunk_mma(acc, f, sb + (c & 3) * STG);
    }
#undef LOADST

    // epilogue: silu(gate) * u -> fp16 activations
#pragma unroll
    for (int mi = 0; mi < 4; mi++) {
        int r0 = m0 + wm * 64 + mi * 16 + (int)qr;
        int r1 = r0 + 8;
#pragma unroll
        for (int ni = 0; ni < 4; ni++) {
            float* u = acc[mi][ni];
            float* g = acc[mi][ni + 4];
            int hcol = hb + wn * 32 + ni * 8 + (int)qc * 2;
            if (r0 < Me) {
                float g0 = g[0], g1 = g[1];
                float v0 = u[0] * (g0 / (1.f + __expf(-g0)));
                float v1 = u[1] * (g1 / (1.f + __expf(-g1)));
                *(__half2*)(g_acth + (size_t)(base + r0) * H_DIM + hcol) = __floats2half2_rn(v0, v1);
            }
            if (r1 < Me) {
                float g2 = g[2], g3 = g[3];
                float v2 = u[2] * (g2 / (1.f + __expf(-g2)));
                float v3 = u[3] * (g3 / (1.f + __expf(-g3)));
                *(__half2*)(g_acth + (size_t)(base + r1) * H_DIM + hcol) = __floats2half2_rn(v2, v3);
            }
        }
    }
}

// ================= fc2: [Me x 2048] x W2^T, weighted scatter-add =================
__global__ __launch_bounds__(256, 1) void fc2_mma(float* __restrict__ y) {
    int e  = blockIdx.z, Me = g_counts[e];
    int m0 = blockIdx.x * 128;
    if (m0 >= Me) return;
    int base = g_offsets[e];
    int n0   = blockIdx.y * 256;

    extern __shared__ char smem[];
    uint32_t sb = smem_u32(smem);
    int tid = threadIdx.x, lane = tid & 31, wid = tid >> 5;
    int wm = wid & 1, wn = wid >> 1;
    uint32_t qr = lane >> 2, qc = lane & 3;

    int arow = tid >> 1;
    int mrow = m0 + arow; if (mrow > Me - 1) mrow = Me - 1;
    const __half* agp = g_acth + (size_t)(base + mrow) * H_DIM + (tid & 1) * 32;
    uint32_t adst[4];
#pragma unroll
    for (int j = 0; j < 4; j++) {
        int cc = (tid & 1) * 4 + j;
        adst[j] = arow * 128 + ((cc * 16) ^ ((arow & 7) << 4));
    }
    int brow = tid;
    const __half* bgp = g_w2h + (size_t)e * D_DIM * H_DIM + (size_t)(n0 + brow) * H_DIM;
    uint32_t bdst[8];
#pragma unroll
    for (int j = 0; j < 8; j++)
        bdst[j] = ASTG + brow * 128 + ((j * 16) ^ ((brow & 7) << 4));

#define LOADST(c, st) do { \
        uint32_t so = sb + (st) * STG; \
        const __half* a_ = agp + (c) * KC; \
        const __half* b_ = bgp + (c) * KC; \
        _Pragma("unroll") for (int j = 0; j < 4; j++) CP16(so + adst[j], a_ + j * 8); \
        _Pragma("unroll") for (int j = 0; j < 8; j++) CP16(so + bdst[j], b_ + j * 8); \
    } while (0)

    float acc[4][8][4];
#pragma unroll
    for (int i = 0; i < 4; i++)
#pragma unroll
        for (int j = 0; j < 8; j++)
#pragma unroll
            for (int k = 0; k < 4; k++) acc[i][j][k] = 0.f;

    Frag f; frag_setup(f, lane, wm, wn);

    const int NC = H_DIM / KC;  // 32
    LOADST(0, 0); CPCOMMIT();
    LOADST(1, 1); CPCOMMIT();
    LOADST(2, 2); CPCOMMIT();

    for (int c = 0; c < NC; c++) {
        CPWAIT2();
        __syncthreads();
        int cn = c + 3;
        if (cn < NC) LOADST(cn, cn & 3);
        CPCOMMIT();
        chunk_mma(acc, f, sb + (c & 3) * STG);
    }
#undef LOADST

    // epilogue: weighted scatter-add into y
#pragma unroll
    for (int mi = 0; mi < 4; mi++) {
        int r0 = m0 + wm * 64 + mi * 16 + (int)qr;
        int r1 = r0 + 8;
        int   t0 = 0, t1 = 0;
        float w0 = 0.f, w1 = 0.f;
        bool v0 = (r0 < Me), v1 = (r1 < Me);
        if (v0) { t0 = g_tok[base + r0]; w0 = g_gw[base + r0]; }
        if (v1) { t1 = g_tok[base + r1]; w1 = g_gw[base + r1]; }
#pragma unroll
        for (int ni = 0; ni < 8; ni++) {
            int col = n0 + wn * 64 + ni * 8 + (int)qc * 2;
            float* c = acc[mi][ni];
            if (v0) {
                atomicAdd(y + (size_t)t0 * D_DIM + col,     c[0] * w0);
                atomicAdd(y + (size_t)t0 * D_DIM + col + 1, c[1] * w0);
            }
            if (v1) {
                atomicAdd(y + (size_t)t1 * D_DIM + col,     c[2] * w1);
                atomicAdd(y + (size_t)t1 * D_DIM + col + 1, c[3] * w1);
            }
        }
    }
}

// ---------------- launch ----------------
extern "C" void kernel_launch(void* const* d_in, const int* in_sizes, int n_in,
                              void* d_out, int out_size) {
    const float* x   = (const float*)d_in[0];
    const float* w   = (const float*)d_in[1];
    const void*  idx = d_in[2];
    const float* W1  = (const float*)d_in[3];
    const float* W2  = (const float*)d_in[4];
    float* y = (float*)d_out;

    cudaFuncSetAttribute(fc1_mma, cudaFuncAttributeMaxDynamicSharedMemorySize, SMEMSZ);
    cudaFuncSetAttribute(fc2_mma, cudaFuncAttributeMaxDynamicSharedMemorySize, SMEMSZ);

    void* xh_p;  cudaGetSymbolAddress(&xh_p,  g_xh);
    void* w1h_p; cudaGetSymbolAddress(&w1h_p, g_w1h);
    void* w2h_p; cudaGetSymbolAddress(&w2h_p, g_w2h);

    int n4 = T_TOK * D_DIM / 4;
    zero_y_kernel<<<(n4 + 255) / 256, 256>>>((float4*)y, n4);                        // 1
    f2h_kernel<<<T_TOK * D_DIM / 8 / 256, 256>>>((const float4*)x, (uint4*)xh_p);    // 2
    f2h_kernel<<<(size_t)E_EXP * 2 * H_DIM * D_DIM / 8 / 256, 256>>>
        ((const float4*)W1, (uint4*)w1h_p);                                          // 3
    f2h_kernel<<<(size_t)E_EXP * D_DIM * H_DIM / 8 / 256, 256>>>
        ((const float4*)W2, (uint4*)w2h_p);                                          // 4
    route_fused<<<1, 256>>>(idx, w);                                                 // 5

    dim3 g1(RMAX / 128, H_DIM / 128, E_EXP);   // (64, 16, 8)
    fc1_mma<<<g1, 256, SMEMSZ>>>();                                                  // 6 <- ncu

    dim3 g2(RMAX / 128, D_DIM / 256, E_EXP);   // (64, 4, 8)
    fc2_mma<<<g2, 256, SMEMSZ>>>(y);                                                 // 7
}

// round 6
// speedup vs baseline: 5.0546x; 1.2883x over previous
#include <cuda_runtime.h>
#include <cuda_fp16.h>
#include <cstdint>

#define T_TOK 4096
#define D_DIM 1024
#define H_DIM 2048
#define E_EXP 8
#define K_TOP 2
#define RMAX (T_TOK * K_TOP)

// ---------------- device scratch (no allocation allowed) ----------------
__device__ int    g_counts[E_EXP];
__device__ int    g_offsets[E_EXP + 1];
__device__ int    g_tok[RMAX];
__device__ float  g_gw[RMAX];
__device__ __half g_acth[(size_t)RMAX * H_DIM];               // fc1 activations, fp16
__device__ __half g_xh[(size_t)T_TOK * D_DIM];                // x in fp16
__device__ __half g_w1h[(size_t)E_EXP * 2 * H_DIM * D_DIM];   // W1 fp16
__device__ __half g_w2h[(size_t)E_EXP * D_DIM * H_DIM];       // W2 fp16

// ---------------- helpers ----------------
__device__ __forceinline__ uint32_t smem_u32(const void* p) {
    uint32_t a;
    asm("{ .reg .u64 t; cvta.to.shared.u64 t, %1; cvt.u32.u64 %0, t; }" : "=r"(a) : "l"(p));
    return a;
}
__device__ __forceinline__ void ldm_x4(uint32_t (&r)[4], uint32_t addr) {
    asm volatile("ldmatrix.sync.aligned.m8n8.x4.shared.b16 {%0,%1,%2,%3}, [%4];"
        : "=r"(r[0]), "=r"(r[1]), "=r"(r[2]), "=r"(r[3]) : "r"(addr));
}
#define CP16(d, s)  asm volatile("cp.async.cg.shared.global [%0], [%1], 16;" :: "r"(d), "l"(s))
#define CPCOMMIT()  asm volatile("cp.async.commit_group;" ::: "memory")
#define CPWAIT1()   asm volatile("cp.async.wait_group 1;" ::: "memory")

#define MMA16(c, a, b0, b1) \
    asm volatile("mma.sync.aligned.m16n8k16.row.col.f32.f16.f16.f32 " \
        "{%0,%1,%2,%3},{%4,%5,%6,%7},{%8,%9},{%0,%1,%2,%3};" \
        : "+f"((c)[0]), "+f"((c)[1]), "+f"((c)[2]), "+f"((c)[3]) \
        : "r"((a)[0]), "r"((a)[1]), "r"((a)[2]), "r"((a)[3]), "r"(b0), "r"(b1))

#define KC 64                        // K halves per chunk (128 B rows)
#define ASTG (128 * 128)             // 16 KB A per stage
#define BSTG (128 * 128)             // 16 KB B per stage (128 rows)
#define STG  (ASTG + BSTG)           // 32 KB
#define SMEMSZ (3 * STG)             // 96 KB -> 2 CTAs/SM

// ---------------- small kernels ----------------
__global__ void zero_y_kernel(float4* y4, int n4) {
    int i = blockIdx.x * blockDim.x + threadIdx.x;
    if (i < n4) y4[i] = make_float4(0.f, 0.f, 0.f, 0.f);
}
__global__ void f2h_kernel(const float4* __restrict__ src, uint4* __restrict__ dst) {
    int i = blockIdx.x * 256 + threadIdx.x;
    float4 a = src[2 * i], b = src[2 * i + 1];
    __half2 h0 = __floats2half2_rn(a.x, a.y);
    __half2 h1 = __floats2half2_rn(a.z, a.w);
    __half2 h2 = __floats2half2_rn(b.x, b.y);
    __half2 h3 = __floats2half2_rn(b.z, b.w);
    uint4 o;
    o.x = *(uint32_t*)&h0; o.y = *(uint32_t*)&h1;
    o.z = *(uint32_t*)&h2; o.w = *(uint32_t*)&h3;
    dst[i] = o;
}
__global__ void route_fused(const void* __restrict__ idxp, const float* __restrict__ w) {
    __shared__ int cnt[E_EXP], off[E_EXP], cur[E_EXP];
    __shared__ int is64s;
    int t = threadIdx.x;
    if (t < E_EXP) { cnt[t] = 0; cur[t] = 0; }
    if (t == 0) is64s = 1;
    __syncthreads();
    const int* i32 = (const int*)idxp;
    for (int i = t; i < RMAX; i += 1024)
        if ((i & 1) && i32[i] != 0) is64s = 0;
    __syncthreads();
    int is64 = is64s;
    for (int i = t; i < RMAX; i += 1024) {
        int e = is64 ? (int)((const long long*)idxp)[i] : i32[i];
        atomicAdd(&cnt[e], 1);
    }
    __syncthreads();
    if (t == 0) {
        int s = 0;
        for (int e = 0; e < E_EXP; e++) {
            off[e] = s; g_offsets[e] = s; g_counts[e] = cnt[e]; s += cnt[e];
        }
        g_offsets[E_EXP] = s;
    }
    __syncthreads();
    for (int i = t; i < RMAX; i += 1024) {
        int e = is64 ? (int)((const long long*)idxp)[i] : i32[i];
        int p = atomicAdd(&cur[e], 1);
        int slot = off[e] + p;
        g_tok[slot] = i / K_TOP;
        g_gw[slot]  = w[i];
    }
}

// ---------------- fragments: warp tile 64(M) x 32(N) ----------------
// Per k16-slice: 4 A ldm_x4 (m16xk16) + 2 B ldm_x4 (n16xk16), 16 MMA16.
struct Frag { uint32_t aRow[4]; uint32_t bRow[2]; uint32_t kA[4]; uint32_t kB[4]; };

__device__ __forceinline__ void frag_setup(Frag& f, int lane, int wm, int wn) {
    int lane7 = lane & 7, lg = lane >> 3;
    uint32_t swz = (uint32_t)lane7 << 4;
#pragma unroll
    for (int mi = 0; mi < 4; mi++)
        f.aRow[mi] = (uint32_t)(wm * 64 + mi * 16 + lane7 + ((lg & 1) << 3)) * 128;
#pragma unroll
    for (int nj = 0; nj < 2; nj++)
        f.bRow[nj] = ASTG + (uint32_t)(wn * 32 + nj * 16 + lane7 + ((lg >> 1) << 3)) * 128;
#pragma unroll
    for (int ks = 0; ks < 4; ks++) {
        f.kA[ks] = ((uint32_t)(ks * 32) + (((uint32_t)lg >> 1) << 4)) ^ swz;
        f.kB[ks] = ((uint32_t)(ks * 32) + (((uint32_t)lg & 1) << 4)) ^ swz;
    }
}

__device__ __forceinline__ void chunk_mma(float (&acc)[4][4][4], const Frag& f, uint32_t Ab) {
#pragma unroll
    for (int ks = 0; ks < 4; ks++) {
        uint32_t Af[4][4], Bq[2][4];
#pragma unroll
        for (int mi = 0; mi < 4; mi++) ldm_x4(Af[mi], Ab + f.aRow[mi] + f.kA[ks]);
#pragma unroll
        for (int nj = 0; nj < 2; nj++) ldm_x4(Bq[nj], Ab + f.bRow[nj] + f.kB[ks]);
#pragma unroll
        for (int mi = 0; mi < 4; mi++)
#pragma unroll
            for (int ni = 0; ni < 4; ni++) {
                const uint32_t* bq = Bq[ni >> 1] + ((ni & 1) << 1);
                MMA16(acc[mi][ni], Af[mi], bq[0], bq[1]);
            }
    }
}

// 3-stage single-sync mainloop body (prologue: load 0,1)
#define MAINLOOP(NC) \
    LOADST(0, 0); CPCOMMIT(); \
    LOADST(1, 1); CPCOMMIT(); \
    { int st = 0, stp = 2; \
      for (int c = 0; c < (NC); c++) { \
        CPWAIT1(); \
        __syncthreads(); \
        int cn = c + 2; \
        if (cn < (NC)) LOADST(cn, stp); \
        CPCOMMIT(); \
        chunk_mma(acc, f, sb + st * STG); \
        st = (st == 2) ? 0 : st + 1; \
        stp = (stp == 2) ? 0 : stp + 1; \
      } }

// ================= fc1: gathered [Me x 1024] x W1^T, fused SwiGLU =================
// Block 128(M) x 128(N=64 u + 64 gate, interleaved per n8 tile).
__global__ __launch_bounds__(256, 2) void fc1_mma() {
    int e  = blockIdx.z, Me = g_counts[e];
    int m0 = blockIdx.x * 128;
    if (m0 >= Me) return;
    int base = g_offsets[e];
    int hb   = blockIdx.y * 64;      // 64 h-cols per block

    extern __shared__ char smem[];
    uint32_t sb = smem_u32(smem);
    int tid = threadIdx.x, lane = tid & 31, wid = tid >> 5;
    int wm = wid & 1, wn = wid >> 1;
    uint32_t qr = lane >> 2, qc = lane & 3;

    // A loader: 2 threads/row, 4x16B
    int arow = tid >> 1;
    int mrow = m0 + arow; if (mrow > Me - 1) mrow = Me - 1;
    const __half* agp = g_xh + (size_t)g_tok[base + mrow] * D_DIM + (tid & 1) * 32;
    uint32_t adst[4];
#pragma unroll
    for (int j = 0; j < 4; j++) {
        int cc = (tid & 1) * 4 + j;
        adst[j] = arow * 128 + ((cc * 16) ^ ((arow & 7) << 4));
    }
    // B loader: 2 threads/row; row brow: n8-tile q=brow>>3; q even = u, q odd = gate
    int brow = tid >> 1;
    int hrow = hb + ((brow >> 4) << 3) + (brow & 7);
    int grow = ((brow >> 3) & 1) ? (H_DIM + hrow) : hrow;
    const __half* bgp = g_w1h + (size_t)e * 2 * H_DIM * D_DIM + (size_t)grow * D_DIM + (tid & 1) * 32;
    uint32_t bdst[4];
#pragma unroll
    for (int j = 0; j < 4; j++) {
        int cc = (tid & 1) * 4 + j;
        bdst[j] = ASTG + brow * 128 + ((cc * 16) ^ ((brow & 7) << 4));
    }

#define LOADST(c, st) do { \
        uint32_t so = sb + (st) * STG; \
        const __half* a_ = agp + (c) * KC; \
        const __half* b_ = bgp + (c) * KC; \
        _Pragma("unroll") for (int j = 0; j < 4; j++) CP16(so + adst[j], a_ + j * 8); \
        _Pragma("unroll") for (int j = 0; j < 4; j++) CP16(so + bdst[j], b_ + j * 8); \
    } while (0)

    float acc[4][4][4];
#pragma unroll
    for (int i = 0; i < 4; i++)
#pragma unroll
        for (int j = 0; j < 4; j++)
#pragma unroll
            for (int k = 0; k < 4; k++) acc[i][j][k] = 0.f;

    Frag f; frag_setup(f, lane, wm, wn);

    MAINLOOP(D_DIM / KC)   // 16 chunks
#undef LOADST

    // epilogue: nj even = u tile, nj odd = gate tile for same 8 h-cols
#pragma unroll
    for (int mi = 0; mi < 4; mi++) {
        int r0 = m0 + wm * 64 + mi * 16 + (int)qr;
        int r1 = r0 + 8;
#pragma unroll
        for (int njp = 0; njp < 2; njp++) {
            float* u = acc[mi][njp * 2];
            float* g = acc[mi][njp * 2 + 1];
            int hcol = hb + (wn * 2 + njp) * 8 + (int)qc * 2;
            if (r0 < Me) {
                float g0 = g[0], g1 = g[1];
                float v0 = u[0] * (g0 / (1.f + __expf(-g0)));
                float v1 = u[1] * (g1 / (1.f + __expf(-g1)));
                *(__half2*)(g_acth + (size_t)(base + r0) * H_DIM + hcol) = __floats2half2_rn(v0, v1);
            }
            if (r1 < Me) {
                float g2 = g[2], g3 = g[3];
                float v2 = u[2] * (g2 / (1.f + __expf(-g2)));
                float v3 = u[3] * (g3 / (1.f + __expf(-g3)));
                *(__half2*)(g_acth + (size_t)(base + r1) * H_DIM + hcol) = __floats2half2_rn(v2, v3);
            }
        }
    }
}

// ================= fc2: [Me x 2048] x W2^T, split-K=2, weighted scatter-add =================
__global__ __launch_bounds__(256, 2) void fc2_mma(float* __restrict__ y) {
    int ez = blockIdx.z;
    int e  = ez >> 1, kh = ez & 1;
    int Me = g_counts[e];
    int m0 = blockIdx.x * 128;
    if (m0 >= Me) return;
    int base = g_offsets[e];
    int n0   = blockIdx.y * 128;
    int k0   = kh * (H_DIM / 2);     // 1024 halves

    extern __shared__ char smem[];
    uint32_t sb = smem_u32(smem);
    int tid = threadIdx.x, lane = tid & 31, wid = tid >> 5;
    int wm = wid & 1, wn = wid >> 1;
    uint32_t qr = lane >> 2, qc = lane & 3;

    int arow = tid >> 1;
    int mrow = m0 + arow; if (mrow > Me - 1) mrow = Me - 1;
    const __half* agp = g_acth + (size_t)(base + mrow) * H_DIM + k0 + (tid & 1) * 32;
    uint32_t adst[4];
#pragma unroll
    for (int j = 0; j < 4; j++) {
        int cc = (tid & 1) * 4 + j;
        adst[j] = arow * 128 + ((cc * 16) ^ ((arow & 7) << 4));
    }
    int brow = tid >> 1;
    const __half* bgp = g_w2h + (size_t)e * D_DIM * H_DIM + (size_t)(n0 + brow) * H_DIM + k0 + (tid & 1) * 32;
    uint32_t bdst[4];
#pragma unroll
    for (int j = 0; j < 4; j++) {
        int cc = (tid & 1) * 4 + j;
        bdst[j] = ASTG + brow * 128 + ((cc * 16) ^ ((brow & 7) << 4));
    }

#define LOADST(c, st) do { \
        uint32_t so = sb + (st) * STG; \
        const __half* a_ = agp + (c) * KC; \
        const __half* b_ = bgp + (c) * KC; \
        _Pragma("unroll") for (int j = 0; j < 4; j++) CP16(so + adst[j], a_ + j * 8); \
        _Pragma("unroll") for (int j = 0; j < 4; j++) CP16(so + bdst[j], b_ + j * 8); \
    } while (0)

    float acc[4][4][4];
#pragma unroll
    for (int i = 0; i < 4; i++)
#pragma unroll
        for (int j = 0; j < 4; j++)
#pragma unroll
            for (int k = 0; k < 4; k++) acc[i][j][k] = 0.f;

    Frag f; frag_setup(f, lane, wm, wn);

    MAINLOOP(H_DIM / 2 / KC)   // 16 chunks per K-half
#undef LOADST

    // epilogue: weighted scatter-add
#pragma unroll
    for (int mi = 0; mi < 4; mi++) {
        int r0 = m0 + wm * 64 + mi * 16 + (int)qr;
        int r1 = r0 + 8;
        int   t0 = 0, t1 = 0;
        float w0 = 0.f, w1 = 0.f;
        bool v0 = (r0 < Me), v1 = (r1 < Me);
        if (v0) { t0 = g_tok[base + r0]; w0 = g_gw[base + r0]; }
        if (v1) { t1 = g_tok[base + r1]; w1 = g_gw[base + r1]; }
#pragma unroll
        for (int ni = 0; ni < 4; ni++) {
            int col = n0 + wn * 32 + ni * 8 + (int)qc * 2;
            float* c = acc[mi][ni];
            if (v0) {
                atomicAdd(y + (size_t)t0 * D_DIM + col,     c[0] * w0);
                atomicAdd(y + (size_t)t0 * D_DIM + col + 1, c[1] * w0);
            }
            if (v1) {
                atomicAdd(y + (size_t)t1 * D_DIM + col,     c[2] * w1);
                atomicAdd(y + (size_t)t1 * D_DIM + col + 1, c[3] * w1);
            }
        }
    }
}

// ---------------- launch ----------------
extern "C" void kernel_launch(void* const* d_in, const int* in_sizes, int n_in,
                              void* d_out, int out_size) {
    const float* x   = (const float*)d_in[0];
    const float* w   = (const float*)d_in[1];
    const void*  idx = d_in[2];
    const float* W1  = (const float*)d_in[3];
    const float* W2  = (const float*)d_in[4];
    float* y = (float*)d_out;

    cudaFuncSetAttribute(fc1_mma, cudaFuncAttributeMaxDynamicSharedMemorySize, SMEMSZ);
    cudaFuncSetAttribute(fc2_mma, cudaFuncAttributeMaxDynamicSharedMemorySize, SMEMSZ);

    void* xh_p;  cudaGetSymbolAddress(&xh_p,  g_xh);
    void* w1h_p; cudaGetSymbolAddress(&w1h_p, g_w1h);
    void* w2h_p; cudaGetSymbolAddress(&w2h_p, g_w2h);

    // launch order tuned so fc1_mma is my 0-based launch #3 (= ncu's -s 5 window)
    f2h_kernel<<<T_TOK * D_DIM / 8 / 256, 256>>>((const float4*)x, (uint4*)xh_p);    // 0
    f2h_kernel<<<(size_t)E_EXP * 2 * H_DIM * D_DIM / 8 / 256, 256>>>
        ((const float4*)W1, (uint4*)w1h_p);                                          // 1
    route_fused<<<1, 1024>>>(idx, w);                                                // 2

    dim3 g1(RMAX / 128, H_DIM / 64, E_EXP);    // (64, 32, 8)
    fc1_mma<<<g1, 256, SMEMSZ>>>();                                                  // 3 <- ncu

    f2h_kernel<<<(size_t)E_EXP * D_DIM * H_DIM / 8 / 256, 256>>>
        ((const float4*)W2, (uint4*)w2h_p);                                          // 4
    int n4 = T_TOK * D_DIM / 4;
    zero_y_kernel<<<(n4 + 255) / 256, 256>>>((float4*)y, n4);                        // 5

    dim3 g2(RMAX / 128, D_DIM / 128, E_EXP * 2);   // (64, 8, 16)
    fc2_mma<<<g2, 256, SMEMSZ>>>(y);                                                 // 6
}